// round 2
// baseline (speedup 1.0000x reference)
#include <cuda_runtime.h>
#include <math.h>

// ---------------- problem constants ----------------
constexpr int CB = 4;                 // batch
constexpr int CH = 128, CW = 128;     // spatial
constexpr int CT = CH * CW;           // 16384 tokens
constexpr int CC = 256;               // channels
constexpr int CM = CB * CT;           // 65536 rows
constexpr int NEL = CM * CC;          // 16,777,216 elements per (B,T,C) tensor

// ---------------- device scratch (static, no allocations) ----------------
// Lifetimes:
//   g_mid     : conv1 out, consumed by dwconv
//   g_dwcat   : dw outputs (K=768), consumed by proj GEMM
//   g_xx      : x + proj sums; later reused to hold gated LN output
//   g_xkvr    : xk|xv|xr, consumed by kvr GEMM
//   g_kvr     : k|v|r ; k,v consumed by wkv, r by lngate
//   g_y       : wkv out, consumed by lngate
__device__ float g_mid[NEL];
__device__ float g_dwcat[3 * NEL];
__device__ float g_xx[NEL];
__device__ float g_xkvr[3 * NEL];
__device__ float g_kvr[3 * NEL];
__device__ float g_y[NEL];
__device__ float g_wcat[CC * 3 * CC]; // concat proj weights (256 x 768)

// ---------------- tiled fp32 GEMM:  out[m,n] = sum_k A[m,k] * W[n,k] ----------------
// M = 65536, N = 256 per z-slice. BM=BN=128, BK=16, 256 threads, 8x8 per thread.
// If BATCH3: blockIdx.z selects (A + z*NEL, Wz = Wtab[z], out + z*NEL).
template <int K, bool ADD, bool BATCH3>
__global__ void __launch_bounds__(256, 2)
sgemm_k(const float* __restrict__ A, const float* __restrict__ W0,
        const float* __restrict__ W1, const float* __restrict__ W2,
        const float* __restrict__ ADDS, float* __restrict__ out)
{
    __shared__ float As[16][128];
    __shared__ float Ws[16][128];

    const int tid = threadIdx.x;
    const int m0 = blockIdx.y * 128;
    const int n0 = blockIdx.x * 128;
    const int tx = tid & 15;
    const int ty = tid >> 4;
    const int lrow = tid >> 2;
    const int lk = (tid & 3) << 2;

    const float* Ause = A;
    const float* Wuse = W0;
    float* ouse = out;
    if (BATCH3) {
        const int z = blockIdx.z;
        Ause = A + (size_t)z * NEL;
        Wuse = (z == 0) ? W0 : (z == 1 ? W1 : W2);
        ouse = out + (size_t)z * NEL;
    }

    const float* Aptr = Ause + (size_t)(m0 + lrow) * K + lk;
    const float* Wptr = Wuse + (size_t)(n0 + lrow) * K + lk;

    float acc[8][8];
#pragma unroll
    for (int i = 0; i < 8; i++)
#pragma unroll
        for (int j = 0; j < 8; j++) acc[i][j] = 0.f;

    for (int k0 = 0; k0 < K; k0 += 16) {
        float4 a0 = *(const float4*)(Aptr + k0);
        float4 a1 = *(const float4*)(Aptr + k0 + (size_t)64 * K);
        float4 w0 = *(const float4*)(Wptr + k0);
        float4 w1 = *(const float4*)(Wptr + k0 + (size_t)64 * K);
        if (k0) __syncthreads();
        As[lk + 0][lrow] = a0.x; As[lk + 1][lrow] = a0.y;
        As[lk + 2][lrow] = a0.z; As[lk + 3][lrow] = a0.w;
        As[lk + 0][lrow + 64] = a1.x; As[lk + 1][lrow + 64] = a1.y;
        As[lk + 2][lrow + 64] = a1.z; As[lk + 3][lrow + 64] = a1.w;
        Ws[lk + 0][lrow] = w0.x; Ws[lk + 1][lrow] = w0.y;
        Ws[lk + 2][lrow] = w0.z; Ws[lk + 3][lrow] = w0.w;
        Ws[lk + 0][lrow + 64] = w1.x; Ws[lk + 1][lrow + 64] = w1.y;
        Ws[lk + 2][lrow + 64] = w1.z; Ws[lk + 3][lrow + 64] = w1.w;
        __syncthreads();
#pragma unroll
        for (int kk = 0; kk < 16; kk++) {
            float av[8], bv[8];
            *(float4*)&av[0] = *(const float4*)&As[kk][ty * 8];
            *(float4*)&av[4] = *(const float4*)&As[kk][ty * 8 + 4];
            *(float4*)&bv[0] = *(const float4*)&Ws[kk][tx * 8];
            *(float4*)&bv[4] = *(const float4*)&Ws[kk][tx * 8 + 4];
#pragma unroll
            for (int i = 0; i < 8; i++)
#pragma unroll
                for (int j = 0; j < 8; j++)
                    acc[i][j] = fmaf(av[i], bv[j], acc[i][j]);
        }
    }

#pragma unroll
    for (int i = 0; i < 8; i++) {
        size_t row = (size_t)(m0 + ty * 8 + i);
        float* op = ouse + row * 256 + n0 + tx * 8;
        float4 r0, r1;
        r0.x = acc[i][0]; r0.y = acc[i][1]; r0.z = acc[i][2]; r0.w = acc[i][3];
        r1.x = acc[i][4]; r1.y = acc[i][5]; r1.z = acc[i][6]; r1.w = acc[i][7];
        if (ADD) {
            const float* ap = ADDS + row * 256 + n0 + tx * 8;
            float4 s0 = *(const float4*)ap;
            float4 s1 = *(const float4*)(ap + 4);
            r0.x += s0.x; r0.y += s0.y; r0.z += s0.z; r0.w += s0.w;
            r1.x += s1.x; r1.y += s1.y; r1.z += s1.z; r1.w += s1.w;
        }
        *(float4*)op = r0;
        *(float4*)(op + 4) = r1;
    }
}

// ---------------- concat proj weights into (256 x 768) ----------------
__global__ void prep_wcat(const float* __restrict__ p1,
                          const float* __restrict__ p2,
                          const float* __restrict__ p3)
{
    int i = blockIdx.x * 256 + threadIdx.x;   // i < 256*768
    int n = i / 768;
    int k = i - n * 768;
    const float* src = (k < 256) ? p1 : (k < 512 ? p2 : p3);
    g_wcat[i] = src[n * 256 + (k & 255)];
}

// ---------------- depthwise 3x3 convs, dilation 1/2/3, 'same' zero pad ----------------
__global__ void dwconv_kernel(const float* __restrict__ w1,
                              const float* __restrict__ w2,
                              const float* __restrict__ w3)
{
    __shared__ float sw[3][256 * 9];
    for (int i = threadIdx.x; i < 256 * 9; i += 256) {
        sw[0][i] = w1[i]; sw[1][i] = w2[i]; sw[2][i] = w3[i];
    }
    __syncthreads();

    const int c = threadIdx.x;
    const int t = blockIdx.x;
    const int b = blockIdx.y;
    const int h = t >> 7, w = t & 127;
    const float* midb = g_mid + (size_t)b * CT * CC;

    float acc1 = 0.f, acc2 = 0.f, acc3 = 0.f;
#pragma unroll
    for (int dy = -1; dy <= 1; dy++) {
#pragma unroll
        for (int dx = -1; dx <= 1; dx++) {
            const int ti = (dy + 1) * 3 + (dx + 1);
            {
                int hh = h + dy, ww = w + dx;
                if ((unsigned)hh < 128u && (unsigned)ww < 128u)
                    acc1 += midb[(size_t)(hh * 128 + ww) * CC + c] * sw[0][c * 9 + ti];
            }
            {
                int hh = h + 2 * dy, ww = w + 2 * dx;
                if ((unsigned)hh < 128u && (unsigned)ww < 128u)
                    acc2 += midb[(size_t)(hh * 128 + ww) * CC + c] * sw[1][c * 9 + ti];
            }
            {
                int hh = h + 3 * dy, ww = w + 3 * dx;
                if ((unsigned)hh < 128u && (unsigned)ww < 128u)
                    acc3 += midb[(size_t)(hh * 128 + ww) * CC + c] * sw[2][c * 9 + ti];
            }
        }
    }
    size_t row = ((size_t)b * CT + t) * 768;
    g_dwcat[row + c]       = acc1;
    g_dwcat[row + 256 + c] = acc2;
    g_dwcat[row + 512 + c] = acc3;
}

// ---------------- token mixing: xk/xv/xr ----------------
__global__ void mix3_kernel(const float* __restrict__ x,
                            const float* __restrict__ mk,
                            const float* __restrict__ mv,
                            const float* __restrict__ mr)
{
    int i = blockIdx.x * 256 + threadIdx.x;
    int c = i & 255;
    float xv = x[i], xxv = g_xx[i];
    float a;
    a = mk[c]; g_xkvr[i]            = xxv + (xv - xxv) * a;
    a = mv[c]; g_xkvr[NEL + i]      = xxv + (xv - xxv) * a;
    a = mr[c]; g_xkvr[2 * NEL + i]  = xxv + (xv - xxv) * a;
}

// ---------------- WKV: chunked parallel scan with decay lookback ----------------
// lambda = exp(-exp(decay/T)) ~ e^-1 for all channels; contributions older than
// 64 steps are < 2e-28 relative -> far below the 1e-3 tolerance.
constexpr int WKV_L = 128;
constexpr int WKV_LB = 64;

__global__ void wkv_kernel(const float* __restrict__ decay,
                           const float* __restrict__ first)
{
    const int c = threadIdx.x;
    const int b = blockIdx.y;
    const int chunk = blockIdx.x;
    const int t0 = chunk * WKV_L;
    int ts = t0 - WKV_LB; if (ts < 0) ts = 0;

    const float lam = expf(-expf(decay[c] * (1.f / CT)));
    const float u = first[c] * (1.f / CT);

    const float* kp = g_kvr + (size_t)b * CT * CC + c;
    const float* vp = kp + NEL;
    float* yp = g_y + (size_t)b * CT * CC + c;

    float a = 0.f, bsum = 0.f;
    for (int t = ts; t < t0; t++) {
        float kk = kp[(size_t)t * CC], vv = vp[(size_t)t * CC];
        float ek = expf(kk);
        a = lam * a + ek * vv;
        bsum = lam * bsum + ek;
    }
    for (int t = t0; t < t0 + WKV_L; t++) {
        float kk = kp[(size_t)t * CC], vv = vp[(size_t)t * CC];
        float e2 = expf(u + kk);
        yp[(size_t)t * CC] = (a + e2 * vv) / (bsum + e2);
        float ek = expf(kk);
        a = lam * a + ek * vv;
        bsum = lam * bsum + ek;
    }
}

// ---------------- LayerNorm + sigmoid gate (one warp per row) ----------------
// Writes gated result into g_xx (reused; its old contents are dead here).
__global__ void lngate_kernel(const float* __restrict__ gamma,
                              const float* __restrict__ beta)
{
    const int warp = threadIdx.x >> 5;
    const int lane = threadIdx.x & 31;
    const size_t row = (size_t)blockIdx.x * 8 + warp;
    const float* yr = g_y + row * CC;
    const float* rr = g_kvr + 2 * (size_t)NEL + row * CC;
    float* gr = g_xx + row * CC;

    float vals[8];
    float s = 0.f;
#pragma unroll
    for (int j = 0; j < 8; j++) { vals[j] = yr[lane + 32 * j]; s += vals[j]; }
#pragma unroll
    for (int o = 16; o; o >>= 1) s += __shfl_xor_sync(0xFFFFFFFFu, s, o);
    const float mu = s * (1.f / 256.f);

    float q = 0.f;
#pragma unroll
    for (int j = 0; j < 8; j++) { float d = vals[j] - mu; q += d * d; }
#pragma unroll
    for (int o = 16; o; o >>= 1) q += __shfl_xor_sync(0xFFFFFFFFu, q, o);
    const float rstd = rsqrtf(q * (1.f / 256.f) + 1e-5f);

#pragma unroll
    for (int j = 0; j < 8; j++) {
        int cidx = lane + 32 * j;
        float sr = 1.f / (1.f + expf(-rr[cidx]));
        gr[cidx] = sr * ((vals[j] - mu) * rstd * gamma[cidx] + beta[cidx]);
    }
}

// ---------------- launch ----------------
extern "C" void kernel_launch(void* const* d_in, const int* in_sizes, int n_in,
                              void* d_out, int out_size)
{
    const float* x        = (const float*)d_in[0];
    const float* conv1_w  = (const float*)d_in[1];
    const float* dw1_w    = (const float*)d_in[2];
    const float* dw2_w    = (const float*)d_in[3];
    const float* dw3_w    = (const float*)d_in[4];
    const float* proj1_w  = (const float*)d_in[5];
    const float* proj2_w  = (const float*)d_in[6];
    const float* proj3_w  = (const float*)d_in[7];
    const float* decay    = (const float*)d_in[8];
    const float* first    = (const float*)d_in[9];
    const float* mix_k    = (const float*)d_in[10];
    const float* mix_v    = (const float*)d_in[11];
    const float* mix_r    = (const float*)d_in[12];
    const float* key_w    = (const float*)d_in[13];
    const float* value_w  = (const float*)d_in[14];
    const float* recep_w  = (const float*)d_in[15];
    const float* out_w    = (const float*)d_in[16];
    const float* ln_gamma = (const float*)d_in[17];
    const float* ln_beta  = (const float*)d_in[18];

    float *mid, *dwcat, *xx, *xkvr, *kvr, *wcat;
    cudaGetSymbolAddress((void**)&mid,   g_mid);
    cudaGetSymbolAddress((void**)&dwcat, g_dwcat);
    cudaGetSymbolAddress((void**)&xx,    g_xx);
    cudaGetSymbolAddress((void**)&xkvr,  g_xkvr);
    cudaGetSymbolAddress((void**)&kvr,   g_kvr);
    cudaGetSymbolAddress((void**)&wcat,  g_wcat);

    const dim3 gGemm(2, 512);       // N/128 x M/128
    const dim3 gGemm3(2, 512, 3);   // batched k/v/r

    // 1) mid = x @ conv1^T
    sgemm_k<256, false, false><<<gGemm, 256>>>(x, conv1_w, nullptr, nullptr, nullptr, mid);
    // 2) depthwise convs -> dwcat (K=768 layout)
    dwconv_kernel<<<dim3(CT, CB), 256>>>(dw1_w, dw2_w, dw3_w);
    // 3) concat proj weights, then xx = x + dwcat @ wcat^T
    prep_wcat<<<768, 256>>>(proj1_w, proj2_w, proj3_w);
    sgemm_k<768, true, false><<<gGemm, 256>>>(dwcat, wcat, nullptr, nullptr, x, xx);
    // 4) token mixing
    mix3_kernel<<<NEL / 256, 256>>>(x, mix_k, mix_v, mix_r);
    // 5) k, v, r projections (batched over z)
    sgemm_k<256, false, true><<<gGemm3, 256>>>(xkvr, key_w, value_w, recep_w, nullptr, kvr);
    // 6) WKV parallel scan
    wkv_kernel<<<dim3(CT / WKV_L, CB), 256>>>(decay, first);
    // 7) LayerNorm + gate -> g_xx
    lngate_kernel<<<CM / 8, 256>>>(ln_gamma, ln_beta);
    // 8) output projection -> d_out
    sgemm_k<256, false, false><<<gGemm, 256>>>(xx, out_w, nullptr, nullptr, nullptr, (float*)d_out);
}

// round 5
// speedup vs baseline: 1.7112x; 1.7112x over previous
#include <cuda_runtime.h>
#include <cuda_bf16.h>
#include <math.h>
#include <stdint.h>

// ---------------- problem constants ----------------
constexpr int CB = 4;
constexpr int CH = 128, CW = 128;
constexpr int CT = CH * CW;           // 16384
constexpr int CC = 256;
constexpr int CM = CB * CT;           // 65536 rows
constexpr int NEL = CM * CC;          // 16.7M floats per tensor

// ---------------- device scratch ----------------
__device__ float g_mid[NEL];
__device__ float g_dwcat[3 * NEL];
__device__ float g_xx[NEL];           // reused: gated LN output
__device__ float g_xkvr[3 * NEL];
__device__ float g_kvr[3 * NEL];
__device__ float g_y[NEL];
__device__ float g_wcat[CC * 3 * CC];

// ---------------- helpers ----------------
__device__ __forceinline__ uint32_t smem_u32(const void* p) {
    uint32_t a;
    asm("{ .reg .u64 t; cvta.to.shared.u64 t, %1; cvt.u32.u64 %0, t; }" : "=r"(a) : "l"(p));
    return a;
}

__device__ __forceinline__ void ldsm4(uint32_t* r, uint32_t addr) {
    asm volatile("ldmatrix.sync.aligned.m8n8.x4.shared.b16 {%0,%1,%2,%3}, [%4];"
                 : "=r"(r[0]), "=r"(r[1]), "=r"(r[2]), "=r"(r[3]) : "r"(addr));
}

__device__ __forceinline__ void mma16816(float* c, const uint32_t* a, const uint32_t* b) {
    asm volatile(
        "mma.sync.aligned.m16n8k16.row.col.f32.bf16.bf16.f32 "
        "{%0,%1,%2,%3}, {%4,%5,%6,%7}, {%8,%9}, {%0,%1,%2,%3};"
        : "+f"(c[0]), "+f"(c[1]), "+f"(c[2]), "+f"(c[3])
        : "r"(a[0]), "r"(a[1]), "r"(a[2]), "r"(a[3]), "r"(b[0]), "r"(b[1]));
}

__device__ __forceinline__ uint32_t pack_bf16(float a, float b) {
    __nv_bfloat162 t = __floats2bfloat162_rn(a, b);
    return *(uint32_t*)&t;
}

__device__ __forceinline__ void split1(float x, float& hf, float& lf) {
    __nv_bfloat16 h = __float2bfloat16_rn(x);
    hf = __bfloat162float(h);
    lf = x - hf;
}

// =====================================================================
// split-bf16 tensor-core GEMM via mma.sync (sm_100 base target, HMMA).
// out[m,n] = sum_k A[m,k] * W[n,k].  CTA tile 128x128, BK=32.
// 8 warps: 4(m) x 2(n); warp tile 32x64; fp32 accumulate.
// 3 passes per chunk: Ahi*Whi + Ahi*Wlo + Alo*Whi (drop lo*lo ~2^-18).
// EPI 0: out = D.  EPI 1: xx=D+xsrc; mix -> out(+0,+NEL,+2NEL).
// NW 3: blockIdx.z batches (A,W,out).
// =====================================================================
// SMEM: 4 tiles of 128 rows x 32 bf16, row stride 40 bf16 (80 B) -> 10240 B each.
constexpr int SROW = 80;              // bytes per smem row
constexpr int SOFF_AHI = 0;
constexpr int SOFF_ALO = 10240;
constexpr int SOFF_BHI = 20480;
constexpr int SOFF_BLO = 30720;

template <int K, int EPI, int NW>
__global__ void __launch_bounds__(256, 2)
mma_gemm(const float* __restrict__ A, const float* __restrict__ W0,
         const float* __restrict__ W1, const float* __restrict__ W2,
         const float* __restrict__ xsrc, const float* __restrict__ mk,
         const float* __restrict__ mv, const float* __restrict__ mr,
         float* __restrict__ out)
{
    __shared__ __align__(16) char sm[40960];
    const int tid = threadIdx.x;
    const int lane = tid & 31;
    const int wid = tid >> 5;
    const int m0 = blockIdx.y * 128;
    const int n0 = blockIdx.x * 128;

    const float* Ause = A;
    const float* Wuse = W0;
    float* ouse = out;
    if (NW == 3) {
        const int z = blockIdx.z;
        Ause = A + (size_t)z * NEL;
        Wuse = (z == 0) ? W0 : (z == 1 ? W1 : W2);
        ouse = out + (size_t)z * NEL;
    }

    const uint32_t sbase = smem_u32(sm);

    // global->smem staging: 2 threads per row, 16 fp32 each
    const int lrow = tid >> 1;            // 0..127
    const int lcol = (tid & 1) * 16;      // 0 or 16
    const float* aptr = Ause + (size_t)(m0 + lrow) * K + lcol;
    const float* wptr = Wuse + (size_t)(n0 + lrow) * K + lcol;
    const uint32_t st_a = sbase + lrow * SROW + lcol * 2;
    const uint32_t st_b = st_a + SOFF_BHI;

    float acc[2][8][4];
#pragma unroll
    for (int i = 0; i < 2; i++)
#pragma unroll
        for (int j = 0; j < 8; j++)
#pragma unroll
            for (int q = 0; q < 4; q++) acc[i][j][q] = 0.f;

    const int mb = (wid >> 1) * 32;       // warp m offset
    const int nb = (wid & 1) * 64;        // warp n offset

    // precomputed ldmatrix addresses (per-lane)
    const uint32_t a_ld = sbase + (mb + (lane & 15)) * SROW + ((lane >> 4) * 8) * 2;
    const uint32_t b_ld = sbase + SOFF_BHI
                        + (nb + (lane & 7) + ((lane >> 4) << 3)) * SROW
                        + (((lane >> 3) & 1) * 8) * 2;

    for (int k0 = 0; k0 < K; k0 += 32) {
        // ---- load chunk from gmem ----
        float4 va[4], vb[4];
#pragma unroll
        for (int i = 0; i < 4; i++) {
            va[i] = *(const float4*)(aptr + k0 + i * 4);
            vb[i] = *(const float4*)(wptr + k0 + i * 4);
        }
        if (k0) __syncthreads();
        // ---- split + store to smem ----
#pragma unroll
        for (int i = 0; i < 4; i++) {
            float h0, l0, h1, l1, h2, l2, h3, l3;
            split1(va[i].x, h0, l0); split1(va[i].y, h1, l1);
            split1(va[i].z, h2, l2); split1(va[i].w, h3, l3);
            *(uint2*)(sm + (st_a - sbase) + SOFF_AHI + i * 8) =
                make_uint2(pack_bf16(h0, h1), pack_bf16(h2, h3));
            *(uint2*)(sm + (st_a - sbase) + SOFF_ALO + i * 8) =
                make_uint2(pack_bf16(l0, l1), pack_bf16(l2, l3));
            split1(vb[i].x, h0, l0); split1(vb[i].y, h1, l1);
            split1(vb[i].z, h2, l2); split1(vb[i].w, h3, l3);
            *(uint2*)(sm + (st_b - sbase) + i * 8) =
                make_uint2(pack_bf16(h0, h1), pack_bf16(h2, h3));
            *(uint2*)(sm + (st_b - sbase) + (SOFF_BLO - SOFF_BHI) + i * 8) =
                make_uint2(pack_bf16(l0, l1), pack_bf16(l2, l3));
        }
        __syncthreads();

        // ---- 3 split passes ----
#pragma unroll
        for (int pass = 0; pass < 3; pass++) {
            const uint32_t aoff = (pass == 2) ? SOFF_ALO : SOFF_AHI;
            const uint32_t boff = (pass == 1) ? (SOFF_BLO - SOFF_BHI) : 0u;
#pragma unroll
            for (int k16 = 0; k16 < 2; k16++) {
                uint32_t af[2][4];
#pragma unroll
                for (int mt = 0; mt < 2; mt++)
                    ldsm4(af[mt], a_ld + aoff + mt * 16 * SROW + k16 * 32);
                uint32_t bf_[4][4];
#pragma unroll
                for (int nt2 = 0; nt2 < 4; nt2++)
                    ldsm4(bf_[nt2], b_ld + boff + nt2 * 16 * SROW + k16 * 32);
#pragma unroll
                for (int mt = 0; mt < 2; mt++)
#pragma unroll
                    for (int nt = 0; nt < 8; nt++)
                        mma16816(acc[mt][nt], af[mt], &bf_[nt >> 1][(nt & 1) * 2]);
            }
        }
    }

    // ---- epilogue ----
    const int r_in = lane >> 2;           // 0..7
    const int c_in = (lane & 3) * 2;      // 0,2,4,6
#pragma unroll
    for (int mt = 0; mt < 2; mt++) {
#pragma unroll
        for (int half = 0; half < 2; half++) {
            const size_t row = (size_t)(m0 + mb + mt * 16 + r_in + half * 8);
#pragma unroll
            for (int nt = 0; nt < 8; nt++) {
                const int c = n0 + nb + nt * 8 + c_in;
                float d0 = acc[mt][nt][half * 2 + 0];
                float d1 = acc[mt][nt][half * 2 + 1];
                if (EPI == 1) {
                    const float* xp = xsrc + row * 256 + c;
                    float x0 = xp[0], x1 = xp[1];
                    float xx0 = d0 + x0, xx1 = d1 + x1;
                    float mk0 = mk[c], mk1 = mk[c + 1];
                    float mv0 = mv[c], mv1 = mv[c + 1];
                    float mr0 = mr[c], mr1 = mr[c + 1];
                    float* ok = ouse + row * 256 + c;
                    *(float2*)ok = make_float2(x0 * mk0 + xx0 * (1.f - mk0),
                                               x1 * mk1 + xx1 * (1.f - mk1));
                    *(float2*)(ok + NEL) = make_float2(x0 * mv0 + xx0 * (1.f - mv0),
                                                       x1 * mv1 + xx1 * (1.f - mv1));
                    *(float2*)(ok + 2 * (size_t)NEL) =
                        make_float2(x0 * mr0 + xx0 * (1.f - mr0),
                                    x1 * mr1 + xx1 * (1.f - mr1));
                } else {
                    *(float2*)(ouse + row * 256 + c) = make_float2(d0, d1);
                }
            }
        }
    }
}

// =====================================================================
// non-GEMM kernels
// =====================================================================
__global__ void prep_wcat(const float* __restrict__ p1,
                          const float* __restrict__ p2,
                          const float* __restrict__ p3)
{
    int i = blockIdx.x * 256 + threadIdx.x;
    int n = i / 768;
    int k = i - n * 768;
    const float* src = (k < 256) ? p1 : (k < 512 ? p2 : p3);
    g_wcat[i] = src[n * 256 + (k & 255)];
}

__global__ void dwconv_kernel(const float* __restrict__ w1,
                              const float* __restrict__ w2,
                              const float* __restrict__ w3)
{
    __shared__ float sw[3][256 * 9];
    for (int i = threadIdx.x; i < 256 * 9; i += 256) {
        sw[0][i] = w1[i]; sw[1][i] = w2[i]; sw[2][i] = w3[i];
    }
    __syncthreads();

    const int c = threadIdx.x;
    const int t = blockIdx.x;
    const int b = blockIdx.y;
    const int h = t >> 7, w = t & 127;
    const float* midb = g_mid + (size_t)b * CT * CC;

    float acc1 = 0.f, acc2 = 0.f, acc3 = 0.f;
#pragma unroll
    for (int dy = -1; dy <= 1; dy++) {
#pragma unroll
        for (int dx = -1; dx <= 1; dx++) {
            const int ti = (dy + 1) * 3 + (dx + 1);
            {
                int hh = h + dy, ww = w + dx;
                if ((unsigned)hh < 128u && (unsigned)ww < 128u)
                    acc1 += midb[(size_t)(hh * 128 + ww) * CC + c] * sw[0][c * 9 + ti];
            }
            {
                int hh = h + 2 * dy, ww = w + 2 * dx;
                if ((unsigned)hh < 128u && (unsigned)ww < 128u)
                    acc2 += midb[(size_t)(hh * 128 + ww) * CC + c] * sw[1][c * 9 + ti];
            }
            {
                int hh = h + 3 * dy, ww = w + 3 * dx;
                if ((unsigned)hh < 128u && (unsigned)ww < 128u)
                    acc3 += midb[(size_t)(hh * 128 + ww) * CC + c] * sw[2][c * 9 + ti];
            }
        }
    }
    size_t row = ((size_t)b * CT + t) * 768;
    g_dwcat[row + c]       = acc1;
    g_dwcat[row + 256 + c] = acc2;
    g_dwcat[row + 512 + c] = acc3;
}

constexpr int WKV_L = 128;
constexpr int WKV_LB = 64;

__global__ void wkv_kernel(const float* __restrict__ decay,
                           const float* __restrict__ first)
{
    const int c = threadIdx.x;
    const int b = blockIdx.y;
    const int t0 = blockIdx.x * WKV_L;
    int ts = t0 - WKV_LB; if (ts < 0) ts = 0;

    const float lam = expf(-expf(decay[c] * (1.f / CT)));
    const float u = first[c] * (1.f / CT);

    const float* kp = g_kvr + (size_t)b * CT * CC + c;
    const float* vp = kp + NEL;
    float* yp = g_y + (size_t)b * CT * CC + c;

    float a = 0.f, bsum = 0.f;
    for (int t = ts; t < t0; t++) {
        float kk = kp[(size_t)t * CC], vv = vp[(size_t)t * CC];
        float ek = expf(kk);
        a = lam * a + ek * vv;
        bsum = lam * bsum + ek;
    }
    for (int t = t0; t < t0 + WKV_L; t++) {
        float kk = kp[(size_t)t * CC], vv = vp[(size_t)t * CC];
        float e2 = expf(u + kk);
        yp[(size_t)t * CC] = (a + e2 * vv) / (bsum + e2);
        float ek = expf(kk);
        a = lam * a + ek * vv;
        bsum = lam * bsum + ek;
    }
}

__global__ void lngate_kernel(const float* __restrict__ gamma,
                              const float* __restrict__ beta)
{
    const int warp = threadIdx.x >> 5;
    const int lane = threadIdx.x & 31;
    const size_t row = (size_t)blockIdx.x * 8 + warp;
    const float* yr = g_y + row * CC;
    const float* rr = g_kvr + 2 * (size_t)NEL + row * CC;
    float* gr = g_xx + row * CC;

    float vals[8];
    float s = 0.f;
#pragma unroll
    for (int j = 0; j < 8; j++) { vals[j] = yr[lane + 32 * j]; s += vals[j]; }
#pragma unroll
    for (int o = 16; o; o >>= 1) s += __shfl_xor_sync(0xFFFFFFFFu, s, o);
    const float mu = s * (1.f / 256.f);

    float q = 0.f;
#pragma unroll
    for (int j = 0; j < 8; j++) { float d = vals[j] - mu; q += d * d; }
#pragma unroll
    for (int o = 16; o; o >>= 1) q += __shfl_xor_sync(0xFFFFFFFFu, q, o);
    const float rstd = rsqrtf(q * (1.f / 256.f) + 1e-5f);

#pragma unroll
    for (int j = 0; j < 8; j++) {
        int cidx = lane + 32 * j;
        float sr = 1.f / (1.f + expf(-rr[cidx]));
        gr[cidx] = sr * ((vals[j] - mu) * rstd * gamma[cidx] + beta[cidx]);
    }
}

// ---------------- launch ----------------
extern "C" void kernel_launch(void* const* d_in, const int* in_sizes, int n_in,
                              void* d_out, int out_size)
{
    const float* x        = (const float*)d_in[0];
    const float* conv1_w  = (const float*)d_in[1];
    const float* dw1_w    = (const float*)d_in[2];
    const float* dw2_w    = (const float*)d_in[3];
    const float* dw3_w    = (const float*)d_in[4];
    const float* proj1_w  = (const float*)d_in[5];
    const float* proj2_w  = (const float*)d_in[6];
    const float* proj3_w  = (const float*)d_in[7];
    const float* decay    = (const float*)d_in[8];
    const float* first    = (const float*)d_in[9];
    const float* mix_k    = (const float*)d_in[10];
    const float* mix_v    = (const float*)d_in[11];
    const float* mix_r    = (const float*)d_in[12];
    const float* key_w    = (const float*)d_in[13];
    const float* value_w  = (const float*)d_in[14];
    const float* recep_w  = (const float*)d_in[15];
    const float* out_w    = (const float*)d_in[16];
    const float* ln_gamma = (const float*)d_in[17];
    const float* ln_beta  = (const float*)d_in[18];

    float *mid, *dwcat, *xx, *xkvr, *kvr, *wcat;
    cudaGetSymbolAddress((void**)&mid,   g_mid);
    cudaGetSymbolAddress((void**)&dwcat, g_dwcat);
    cudaGetSymbolAddress((void**)&xx,    g_xx);
    cudaGetSymbolAddress((void**)&xkvr,  g_xkvr);
    cudaGetSymbolAddress((void**)&kvr,   g_kvr);
    cudaGetSymbolAddress((void**)&wcat,  g_wcat);

    const dim3 gGemm(2, 512);        // n-tiles x m-tiles
    const dim3 gGemm3(2, 512, 3);

    // 1) mid = x @ conv1^T
    mma_gemm<256, 0, 1><<<gGemm, 256>>>(x, conv1_w, nullptr, nullptr,
                                        nullptr, nullptr, nullptr, nullptr, mid);
    // 2) depthwise convs -> dwcat (K=768 layout)
    dwconv_kernel<<<dim3(CT, CB), 256>>>(dw1_w, dw2_w, dw3_w);
    // 3) concat proj weights; fused: xx = x + dwcat@wcat^T; mix -> xk|xv|xr
    prep_wcat<<<768, 256>>>(proj1_w, proj2_w, proj3_w);
    mma_gemm<768, 1, 1><<<gGemm, 256>>>(dwcat, wcat, nullptr, nullptr,
                                        x, mix_k, mix_v, mix_r, xkvr);
    // 4) k, v, r projections (batched over z)
    mma_gemm<256, 0, 3><<<gGemm3, 256>>>(xkvr, key_w, value_w, recep_w,
                                         nullptr, nullptr, nullptr, nullptr, kvr);
    // 5) WKV parallel scan
    wkv_kernel<<<dim3(CT / WKV_L, CB), 256>>>(decay, first);
    // 6) LayerNorm + gate -> g_xx
    lngate_kernel<<<CM / 8, 256>>>(ln_gamma, ln_beta);
    // 7) output projection -> d_out
    mma_gemm<256, 0, 1><<<gGemm, 256>>>(xx, out_w, nullptr, nullptr,
                                        nullptr, nullptr, nullptr, nullptr, (float*)d_out);
}

// round 8
// speedup vs baseline: 1.7378x; 1.0156x over previous
#include <cuda_runtime.h>
#include <cuda_bf16.h>
#include <math.h>
#include <stdint.h>

// ---------------- problem constants ----------------
constexpr int CB = 4;
constexpr int CH = 128, CW = 128;
constexpr int CT = CH * CW;           // 16384
constexpr int CC = 256;
constexpr int CM = CB * CT;           // 65536 rows
constexpr int NEL = CM * CC;          // 16.7M floats per tensor

// ---------------- device scratch ----------------
__device__ float g_mid[NEL];
__device__ float g_dwcat[3 * NEL];
__device__ float g_xx[NEL];           // reused: gated LN output
__device__ float g_xkvr[3 * NEL];
__device__ float g_kvr[3 * NEL];
__device__ float g_y[NEL];
__device__ float g_wcat[CC * 3 * CC];

// ---------------- helpers ----------------
__device__ __forceinline__ uint32_t smem_u32(const void* p) {
    uint32_t a;
    asm("{ .reg .u64 t; cvta.to.shared.u64 t, %1; cvt.u32.u64 %0, t; }" : "=r"(a) : "l"(p));
    return a;
}

__device__ __forceinline__ void ldsm4(uint32_t* r, uint32_t addr) {
    asm volatile("ldmatrix.sync.aligned.m8n8.x4.shared.b16 {%0,%1,%2,%3}, [%4];"
                 : "=r"(r[0]), "=r"(r[1]), "=r"(r[2]), "=r"(r[3]) : "r"(addr));
}

__device__ __forceinline__ void mma16816(float* c, const uint32_t* a, const uint32_t* b) {
    asm volatile(
        "mma.sync.aligned.m16n8k16.row.col.f32.bf16.bf16.f32 "
        "{%0,%1,%2,%3}, {%4,%5,%6,%7}, {%8,%9}, {%0,%1,%2,%3};"
        : "+f"(c[0]), "+f"(c[1]), "+f"(c[2]), "+f"(c[3])
        : "r"(a[0]), "r"(a[1]), "r"(a[2]), "r"(a[3]), "r"(b[0]), "r"(b[1]));
}

__device__ __forceinline__ uint32_t pack_bf16(float a, float b) {
    __nv_bfloat162 t = __floats2bfloat162_rn(a, b);
    return *(uint32_t*)&t;
}

__device__ __forceinline__ void split1(float x, float& hf, float& lf) {
    __nv_bfloat16 h = __float2bfloat16_rn(x);
    hf = __bfloat162float(h);
    lf = x - hf;
}

// split 4 floats -> hi pair-packed (2 u32) + lo pair-packed (2 u32)
__device__ __forceinline__ void split4(float4 v, uint32_t* h, uint32_t* l) {
    float h0, l0, h1, l1, h2, l2, h3, l3;
    split1(v.x, h0, l0); split1(v.y, h1, l1);
    split1(v.z, h2, l2); split1(v.w, h3, l3);
    h[0] = pack_bf16(h0, h1); h[1] = pack_bf16(h2, h3);
    l[0] = pack_bf16(l0, l1); l[1] = pack_bf16(l2, l3);
}

// =====================================================================
// split-bf16 tensor-core GEMM via mma.sync (sm_100 base target, HMMA).
// out[m,n] = sum_k A[m,k] * W[n,k].  CTA tile 128x128, BK=32.
// 8 warps: 4(m) x 2(n); warp tile 32x64; fp32 accumulate.
// Per k16: hold Ahi+Alo (16 regs) and one B set (16 regs):
//   p0 = Ahi*Bhi, p2 = Alo*Bhi, then overwrite B with Blo: p1 = Ahi*Blo.
// (lo*lo term dropped, ~2^-18 relative)
// EPI 0: out = D.  EPI 1: xx=D+xsrc; mix -> out(+0,+NEL,+2NEL).
// NW 3: blockIdx.z batches (A,W,out).
// =====================================================================
constexpr int SROW = 80;              // bytes per smem row (40 bf16)
constexpr int SOFF_AHI = 0;
constexpr int SOFF_ALO = 10240;
constexpr int SOFF_BHI = 20480;
constexpr int SOFF_BLO = 30720;

template <int K, int EPI, int NW>
__global__ void __launch_bounds__(256, 2)
mma_gemm(const float* __restrict__ A, const float* __restrict__ W0,
         const float* __restrict__ W1, const float* __restrict__ W2,
         const float* __restrict__ xsrc, const float* __restrict__ mk,
         const float* __restrict__ mv, const float* __restrict__ mr,
         float* __restrict__ out)
{
    __shared__ __align__(16) char sm[40960];
    const int tid = threadIdx.x;
    const int lane = tid & 31;
    const int wid = tid >> 5;
    const int m0 = blockIdx.y * 128;
    const int n0 = blockIdx.x * 128;

    const float* Ause = A;
    const float* Wuse = W0;
    float* ouse = out;
    if (NW == 3) {
        const int z = blockIdx.z;
        Ause = A + (size_t)z * NEL;
        Wuse = (z == 0) ? W0 : (z == 1 ? W1 : W2);
        ouse = out + (size_t)z * NEL;
    }

    const uint32_t sbase = smem_u32(sm);

    // global->smem staging: 2 threads per row, 16 fp32 each
    const int lrow = tid >> 1;            // 0..127
    const int lcol = (tid & 1) * 16;      // 0 or 16
    const float* aptr = Ause + (size_t)(m0 + lrow) * K + lcol;
    const float* wptr = Wuse + (size_t)(n0 + lrow) * K + lcol;
    const int st_off = lrow * SROW + lcol * 2;   // byte offset within a tile

    float acc[2][8][4];
#pragma unroll
    for (int i = 0; i < 2; i++)
#pragma unroll
        for (int j = 0; j < 8; j++)
#pragma unroll
            for (int q = 0; q < 4; q++) acc[i][j][q] = 0.f;

    const int mb = (wid >> 1) * 32;       // warp m offset
    const int nb = (wid & 1) * 64;        // warp n offset

    // precomputed ldmatrix addresses (per-lane)
    const uint32_t a_ld = sbase + (mb + (lane & 15)) * SROW + ((lane >> 4) * 8) * 2;
    const uint32_t b_ld = sbase + SOFF_BHI
                        + (nb + (lane & 7) + ((lane >> 4) << 3)) * SROW
                        + (((lane >> 3) & 1) * 8) * 2;

    for (int k0 = 0; k0 < K; k0 += 32) {
        // ---- load chunk from gmem ----
        float4 va[4], vb[4];
#pragma unroll
        for (int i = 0; i < 4; i++) {
            va[i] = *(const float4*)(aptr + k0 + i * 4);
            vb[i] = *(const float4*)(wptr + k0 + i * 4);
        }
        if (k0) __syncthreads();
        // ---- split + store to smem (STS.128) ----
        {
            uint32_t ah[8], al[8], bh[8], bl[8];
#pragma unroll
            for (int i = 0; i < 4; i++) {
                split4(va[i], &ah[i * 2], &al[i * 2]);
                split4(vb[i], &bh[i * 2], &bl[i * 2]);
            }
            *(uint4*)(sm + SOFF_AHI + st_off)      = *(uint4*)&ah[0];
            *(uint4*)(sm + SOFF_AHI + st_off + 16) = *(uint4*)&ah[4];
            *(uint4*)(sm + SOFF_ALO + st_off)      = *(uint4*)&al[0];
            *(uint4*)(sm + SOFF_ALO + st_off + 16) = *(uint4*)&al[4];
            *(uint4*)(sm + SOFF_BHI + st_off)      = *(uint4*)&bh[0];
            *(uint4*)(sm + SOFF_BHI + st_off + 16) = *(uint4*)&bh[4];
            *(uint4*)(sm + SOFF_BLO + st_off)      = *(uint4*)&bl[0];
            *(uint4*)(sm + SOFF_BLO + st_off + 16) = *(uint4*)&bl[4];
        }
        __syncthreads();

        // ---- fragment-reuse compute: 12 ldsm4 per k16 (was 18) ----
#pragma unroll
        for (int k16 = 0; k16 < 2; k16++) {
            uint32_t ahf[2][4], alf[2][4], bf_[4][4];
#pragma unroll
            for (int mt = 0; mt < 2; mt++) {
                ldsm4(ahf[mt], a_ld + SOFF_AHI + mt * 16 * SROW + k16 * 32);
                ldsm4(alf[mt], a_ld + SOFF_ALO + mt * 16 * SROW + k16 * 32);
            }
#pragma unroll
            for (int nt2 = 0; nt2 < 4; nt2++)
                ldsm4(bf_[nt2], b_ld + nt2 * 16 * SROW + k16 * 32);
            // p0: Ahi * Bhi
#pragma unroll
            for (int mt = 0; mt < 2; mt++)
#pragma unroll
                for (int nt = 0; nt < 8; nt++)
                    mma16816(acc[mt][nt], ahf[mt], &bf_[nt >> 1][(nt & 1) * 2]);
            // p2: Alo * Bhi
#pragma unroll
            for (int mt = 0; mt < 2; mt++)
#pragma unroll
                for (int nt = 0; nt < 8; nt++)
                    mma16816(acc[mt][nt], alf[mt], &bf_[nt >> 1][(nt & 1) * 2]);
            // overwrite B regs with Blo; p1: Ahi * Blo
#pragma unroll
            for (int nt2 = 0; nt2 < 4; nt2++)
                ldsm4(bf_[nt2], b_ld + (SOFF_BLO - SOFF_BHI) + nt2 * 16 * SROW + k16 * 32);
#pragma unroll
            for (int mt = 0; mt < 2; mt++)
#pragma unroll
                for (int nt = 0; nt < 8; nt++)
                    mma16816(acc[mt][nt], ahf[mt], &bf_[nt >> 1][(nt & 1) * 2]);
        }
    }

    // ---- epilogue ----
    const int r_in = lane >> 2;           // 0..7
    const int c_in = (lane & 3) * 2;      // 0,2,4,6
#pragma unroll
    for (int mt = 0; mt < 2; mt++) {
#pragma unroll
        for (int half = 0; half < 2; half++) {
            const size_t row = (size_t)(m0 + mb + mt * 16 + r_in + half * 8);
#pragma unroll
            for (int nt = 0; nt < 8; nt++) {
                const int c = n0 + nb + nt * 8 + c_in;
                float d0 = acc[mt][nt][half * 2 + 0];
                float d1 = acc[mt][nt][half * 2 + 1];
                if (EPI == 1) {
                    const float* xp = xsrc + row * 256 + c;
                    float x0 = xp[0], x1 = xp[1];
                    float xx0 = d0 + x0, xx1 = d1 + x1;
                    float mk0 = mk[c], mk1 = mk[c + 1];
                    float mv0 = mv[c], mv1 = mv[c + 1];
                    float mr0 = mr[c], mr1 = mr[c + 1];
                    float* ok = ouse + row * 256 + c;
                    *(float2*)ok = make_float2(x0 * mk0 + xx0 * (1.f - mk0),
                                               x1 * mk1 + xx1 * (1.f - mk1));
                    *(float2*)(ok + NEL) = make_float2(x0 * mv0 + xx0 * (1.f - mv0),
                                                       x1 * mv1 + xx1 * (1.f - mv1));
                    *(float2*)(ok + 2 * (size_t)NEL) =
                        make_float2(x0 * mr0 + xx0 * (1.f - mr0),
                                    x1 * mr1 + xx1 * (1.f - mr1));
                } else {
                    *(float2*)(ouse + row * 256 + c) = make_float2(d0, d1);
                }
            }
        }
    }
}

// =====================================================================
// non-GEMM kernels
// =====================================================================
__global__ void prep_wcat(const float* __restrict__ p1,
                          const float* __restrict__ p2,
                          const float* __restrict__ p3)
{
    int i = blockIdx.x * 256 + threadIdx.x;
    int n = i / 768;
    int k = i - n * 768;
    const float* src = (k < 256) ? p1 : (k < 512 ? p2 : p3);
    g_wcat[i] = src[n * 256 + (k & 255)];
}

__global__ void dwconv_kernel(const float* __restrict__ w1,
                              const float* __restrict__ w2,
                              const float* __restrict__ w3)
{
    __shared__ float sw[3][256 * 9];
    for (int i = threadIdx.x; i < 256 * 9; i += 256) {
        sw[0][i] = w1[i]; sw[1][i] = w2[i]; sw[2][i] = w3[i];
    }
    __syncthreads();

    const int c = threadIdx.x;
    const int t = blockIdx.x;
    const int b = blockIdx.y;
    const int h = t >> 7, w = t & 127;
    const float* midb = g_mid + (size_t)b * CT * CC;

    float acc1 = 0.f, acc2 = 0.f, acc3 = 0.f;
#pragma unroll
    for (int dy = -1; dy <= 1; dy++) {
#pragma unroll
        for (int dx = -1; dx <= 1; dx++) {
            const int ti = (dy + 1) * 3 + (dx + 1);
            {
                int hh = h + dy, ww = w + dx;
                if ((unsigned)hh < 128u && (unsigned)ww < 128u)
                    acc1 += midb[(size_t)(hh * 128 + ww) * CC + c] * sw[0][c * 9 + ti];
            }
            {
                int hh = h + 2 * dy, ww = w + 2 * dx;
                if ((unsigned)hh < 128u && (unsigned)ww < 128u)
                    acc2 += midb[(size_t)(hh * 128 + ww) * CC + c] * sw[1][c * 9 + ti];
            }
            {
                int hh = h + 3 * dy, ww = w + 3 * dx;
                if ((unsigned)hh < 128u && (unsigned)ww < 128u)
                    acc3 += midb[(size_t)(hh * 128 + ww) * CC + c] * sw[2][c * 9 + ti];
            }
        }
    }
    size_t row = ((size_t)b * CT + t) * 768;
    g_dwcat[row + c]       = acc1;
    g_dwcat[row + 256 + c] = acc2;
    g_dwcat[row + 512 + c] = acc3;
}

constexpr int WKV_L = 128;
constexpr int WKV_LB = 64;

__global__ void wkv_kernel(const float* __restrict__ decay,
                           const float* __restrict__ first)
{
    const int c = threadIdx.x;
    const int b = blockIdx.y;
    const int t0 = blockIdx.x * WKV_L;
    int ts = t0 - WKV_LB; if (ts < 0) ts = 0;

    const float lam = expf(-expf(decay[c] * (1.f / CT)));
    const float u = first[c] * (1.f / CT);

    const float* kp = g_kvr + (size_t)b * CT * CC + c;
    const float* vp = kp + NEL;
    float* yp = g_y + (size_t)b * CT * CC + c;

    float a = 0.f, bsum = 0.f;
    for (int t = ts; t < t0; t++) {
        float kk = kp[(size_t)t * CC], vv = vp[(size_t)t * CC];
        float ek = expf(kk);
        a = lam * a + ek * vv;
        bsum = lam * bsum + ek;
    }
    for (int t = t0; t < t0 + WKV_L; t++) {
        float kk = kp[(size_t)t * CC], vv = vp[(size_t)t * CC];
        float e2 = expf(u + kk);
        yp[(size_t)t * CC] = (a + e2 * vv) / (bsum + e2);
        float ek = expf(kk);
        a = lam * a + ek * vv;
        bsum = lam * bsum + ek;
    }
}

__global__ void lngate_kernel(const float* __restrict__ gamma,
                              const float* __restrict__ beta)
{
    const int warp = threadIdx.x >> 5;
    const int lane = threadIdx.x & 31;
    const size_t row = (size_t)blockIdx.x * 8 + warp;
    const float* yr = g_y + row * CC;
    const float* rr = g_kvr + 2 * (size_t)NEL + row * CC;
    float* gr = g_xx + row * CC;

    float vals[8];
    float s = 0.f;
#pragma unroll
    for (int j = 0; j < 8; j++) { vals[j] = yr[lane + 32 * j]; s += vals[j]; }
#pragma unroll
    for (int o = 16; o; o >>= 1) s += __shfl_xor_sync(0xFFFFFFFFu, s, o);
    const float mu = s * (1.f / 256.f);

    float q = 0.f;
#pragma unroll
    for (int j = 0; j < 8; j++) { float d = vals[j] - mu; q += d * d; }
#pragma unroll
    for (int o = 16; o; o >>= 1) q += __shfl_xor_sync(0xFFFFFFFFu, q, o);
    const float rstd = rsqrtf(q * (1.f / 256.f) + 1e-5f);

#pragma unroll
    for (int j = 0; j < 8; j++) {
        int cidx = lane + 32 * j;
        float sr = 1.f / (1.f + expf(-rr[cidx]));
        gr[cidx] = sr * ((vals[j] - mu) * rstd * gamma[cidx] + beta[cidx]);
    }
}

// ---------------- launch ----------------
extern "C" void kernel_launch(void* const* d_in, const int* in_sizes, int n_in,
                              void* d_out, int out_size)
{
    const float* x        = (const float*)d_in[0];
    const float* conv1_w  = (const float*)d_in[1];
    const float* dw1_w    = (const float*)d_in[2];
    const float* dw2_w    = (const float*)d_in[3];
    const float* dw3_w    = (const float*)d_in[4];
    const float* proj1_w  = (const float*)d_in[5];
    const float* proj2_w  = (const float*)d_in[6];
    const float* proj3_w  = (const float*)d_in[7];
    const float* decay    = (const float*)d_in[8];
    const float* first    = (const float*)d_in[9];
    const float* mix_k    = (const float*)d_in[10];
    const float* mix_v    = (const float*)d_in[11];
    const float* mix_r    = (const float*)d_in[12];
    const float* key_w    = (const float*)d_in[13];
    const float* value_w  = (const float*)d_in[14];
    const float* recep_w  = (const float*)d_in[15];
    const float* out_w    = (const float*)d_in[16];
    const float* ln_gamma = (const float*)d_in[17];
    const float* ln_beta  = (const float*)d_in[18];

    float *mid, *dwcat, *xx, *xkvr, *kvr, *wcat;
    cudaGetSymbolAddress((void**)&mid,   g_mid);
    cudaGetSymbolAddress((void**)&dwcat, g_dwcat);
    cudaGetSymbolAddress((void**)&xx,    g_xx);
    cudaGetSymbolAddress((void**)&xkvr,  g_xkvr);
    cudaGetSymbolAddress((void**)&kvr,   g_kvr);
    cudaGetSymbolAddress((void**)&wcat,  g_wcat);

    const dim3 gGemm(2, 512);        // n-tiles x m-tiles
    const dim3 gGemm3(2, 512, 3);

    // 1) mid = x @ conv1^T
    mma_gemm<256, 0, 1><<<gGemm, 256>>>(x, conv1_w, nullptr, nullptr,
                                        nullptr, nullptr, nullptr, nullptr, mid);
    // 2) depthwise convs -> dwcat (K=768 layout)
    dwconv_kernel<<<dim3(CT, CB), 256>>>(dw1_w, dw2_w, dw3_w);
    // 3) concat proj weights; fused: xx = x + dwcat@wcat^T; mix -> xk|xv|xr
    prep_wcat<<<768, 256>>>(proj1_w, proj2_w, proj3_w);
    mma_gemm<768, 1, 1><<<gGemm, 256>>>(dwcat, wcat, nullptr, nullptr,
                                        x, mix_k, mix_v, mix_r, xkvr);
    // 4) k, v, r projections (batched over z)
    mma_gemm<256, 0, 3><<<gGemm3, 256>>>(xkvr, key_w, value_w, recep_w,
                                         nullptr, nullptr, nullptr, nullptr, kvr);
    // 5) WKV parallel scan
    wkv_kernel<<<dim3(CT / WKV_L, CB), 256>>>(decay, first);
    // 6) LayerNorm + gate -> g_xx
    lngate_kernel<<<CM / 8, 256>>>(ln_gamma, ln_beta);
    // 7) output projection -> d_out
    mma_gemm<256, 0, 1><<<gGemm, 256>>>(xx, out_w, nullptr, nullptr,
                                        nullptr, nullptr, nullptr, nullptr, (float*)d_out);
}

// round 9
// speedup vs baseline: 1.7941x; 1.0324x over previous
#include <cuda_runtime.h>
#include <cuda_bf16.h>
#include <math.h>
#include <stdint.h>

// ---------------- problem constants ----------------
constexpr int CB = 4;
constexpr int CH = 128, CW = 128;
constexpr int CT = CH * CW;           // 16384
constexpr int CC = 256;
constexpr int CM = CB * CT;           // 65536 rows
constexpr int NEL = CM * CC;          // 16.7M elements per (B,T,C) tensor

// ---------------- device scratch ----------------
__device__ __nv_bfloat16 g_x_sp[2 * NEL];          // split of input x [hi|lo]
__device__ float         g_mid[NEL];               // conv1 out (fp32)
__device__ __nv_bfloat16 g_dw_sp[6 * NEL];         // dwcat split: hi(CM*768) | lo
__device__ __nv_bfloat16 g_xkvr_sp[6 * NEL];       // [khi|klo|vhi|vlo|rhi|rlo]
__device__ float         g_kvr[3 * NEL];           // k|v|r fp32
__device__ float         g_y[NEL];                 // wkv out
__device__ __nv_bfloat16 g_gate_sp[2 * NEL];       // gated LN out split
__device__ __nv_bfloat16 g_w1_sp[2 * 65536];
__device__ __nv_bfloat16 g_wcat_sp[2 * 196608];
__device__ __nv_bfloat16 g_wkvr_sp[6 * 65536];     // [khi|klo|vhi|vlo|rhi|rlo]
__device__ __nv_bfloat16 g_wo_sp[2 * 65536];

// ---------------- helpers ----------------
__device__ __forceinline__ uint32_t smem_u32(const void* p) {
    uint32_t a;
    asm("{ .reg .u64 t; cvta.to.shared.u64 t, %1; cvt.u32.u64 %0, t; }" : "=r"(a) : "l"(p));
    return a;
}

__device__ __forceinline__ void ldsm4(uint32_t* r, uint32_t addr) {
    asm volatile("ldmatrix.sync.aligned.m8n8.x4.shared.b16 {%0,%1,%2,%3}, [%4];"
                 : "=r"(r[0]), "=r"(r[1]), "=r"(r[2]), "=r"(r[3]) : "r"(addr));
}

__device__ __forceinline__ void mma16816(float* c, const uint32_t* a, const uint32_t* b) {
    asm volatile(
        "mma.sync.aligned.m16n8k16.row.col.f32.bf16.bf16.f32 "
        "{%0,%1,%2,%3}, {%4,%5,%6,%7}, {%8,%9}, {%0,%1,%2,%3};"
        : "+f"(c[0]), "+f"(c[1]), "+f"(c[2]), "+f"(c[3])
        : "r"(a[0]), "r"(a[1]), "r"(a[2]), "r"(a[3]), "r"(b[0]), "r"(b[1]));
}

__device__ __forceinline__ void cpa16(uint32_t d, const void* g) {
    asm volatile("cp.async.cg.shared.global [%0], [%1], 16;" :: "r"(d), "l"(g));
}

__device__ __forceinline__ uint32_t pack_bf16(float a, float b) {
    __nv_bfloat162 t = __floats2bfloat162_rn(a, b);
    return *(uint32_t*)&t;
}

__device__ __forceinline__ void split1(float x, float& hf, float& lf) {
    __nv_bfloat16 h = __float2bfloat16_rn(x);
    hf = __bfloat162float(h);
    lf = x - hf;
}

__device__ __forceinline__ void split4(float4 v, uint32_t* h, uint32_t* l) {
    float h0, l0, h1, l1, h2, l2, h3, l3;
    split1(v.x, h0, l0); split1(v.y, h1, l1);
    split1(v.z, h2, l2); split1(v.w, h3, l3);
    h[0] = pack_bf16(h0, h1); h[1] = pack_bf16(h2, h3);
    l[0] = pack_bf16(l0, l1); l[1] = pack_bf16(l2, l3);
}

// =====================================================================
// pre-split bf16 GEMM via mma.sync, cp.async double-buffered.
// D = Ahi*Whi + Alo*Whi + Ahi*Wlo.  A: hi at A, lo at A + CM*K.
// W: hi at W, lo at W + 256*K.  NW3: slice z at +z*2*stride.
// CTA 128x128, BK=32, 8 warps 4x2.
// =====================================================================
constexpr int SROW = 80;
constexpr int TILE = 128 * SROW;      // 10240
constexpr int BUF  = 4 * TILE;        // 40960
constexpr int SMEM_GEMM = 2 * BUF;    // 81920

template <int K, int EPI, int NW>
__global__ void __launch_bounds__(256, 2)
mma_gemm(const __nv_bfloat16* __restrict__ A, const __nv_bfloat16* __restrict__ W,
         const float* __restrict__ xsrc, const float* __restrict__ mk,
         const float* __restrict__ mv, const float* __restrict__ mr,
         float* __restrict__ outf, __nv_bfloat16* __restrict__ outsp)
{
    extern __shared__ __align__(16) char smd[];
    const int tid = threadIdx.x;
    const int lane = tid & 31;
    const int wid = tid >> 5;
    const int m0 = blockIdx.y * 128;
    const int n0 = blockIdx.x * 128;

    const size_t ALOFF = (size_t)CM * K;
    const size_t WLOFF = (size_t)256 * K;

    const __nv_bfloat16* Ah = A;
    const __nv_bfloat16* Wh = W;
    float* ofuse = outf;
    if (NW == 3) {
        const int z = blockIdx.z;
        Ah = A + (size_t)z * 2 * ALOFF;
        Wh = W + (size_t)z * 2 * WLOFF;
        ofuse = outf + (size_t)z * NEL;
    }
    const __nv_bfloat16* Al = Ah + ALOFF;
    const __nv_bfloat16* Wl = Wh + WLOFF;

    const uint32_t sb = smem_u32(smd);

    const int r = tid >> 1;
    const int kc = (tid & 1) * 2;
    const uint32_t dst0 = sb + r * SROW + kc * 16;

    const int mb = (wid >> 1) * 32;
    const int nb = (wid & 1) * 64;
    const uint32_t a_ld0 = sb + (mb + (lane & 15)) * SROW + ((lane >> 4) * 8) * 2;
    const uint32_t b_ld0 = sb + 2 * TILE
                         + (nb + (lane & 7) + ((lane >> 4) << 3)) * SROW
                         + (((lane >> 3) & 1) * 8) * 2;

    float acc[2][8][4];
#pragma unroll
    for (int i = 0; i < 2; i++)
#pragma unroll
        for (int j = 0; j < 8; j++)
#pragma unroll
            for (int q = 0; q < 4; q++) acc[i][j][q] = 0.f;

    constexpr int NCH = K / 32;

    auto issue = [&](int ch, int buf) {
        const size_t ga = (size_t)(m0 + r) * K + ch * 32 + kc * 8;
        const size_t gb = (size_t)(n0 + r) * K + ch * 32 + kc * 8;
        const uint32_t d = dst0 + buf * BUF;
        cpa16(d,                Ah + ga); cpa16(d + 16,            Ah + ga + 8);
        cpa16(d + TILE,         Al + ga); cpa16(d + TILE + 16,     Al + ga + 8);
        cpa16(d + 2 * TILE,     Wh + gb); cpa16(d + 2 * TILE + 16, Wh + gb + 8);
        cpa16(d + 3 * TILE,     Wl + gb); cpa16(d + 3 * TILE + 16, Wl + gb + 8);
        asm volatile("cp.async.commit_group;");
    };

    issue(0, 0);

    for (int ch = 0; ch < NCH; ch++) {
        if (ch + 1 < NCH) {
            issue(ch + 1, (ch + 1) & 1);
            asm volatile("cp.async.wait_group 1;");
        } else {
            asm volatile("cp.async.wait_group 0;");
        }
        __syncthreads();

        const uint32_t bo = (uint32_t)(ch & 1) * BUF;
        const uint32_t a_ld = a_ld0 + bo;
        const uint32_t b_ld = b_ld0 + bo;

#pragma unroll
        for (int k16 = 0; k16 < 2; k16++) {
            uint32_t ahf[2][4], alf[2][4], bf_[4][4];
#pragma unroll
            for (int mt = 0; mt < 2; mt++) {
                ldsm4(ahf[mt], a_ld + mt * 16 * SROW + k16 * 32);
                ldsm4(alf[mt], a_ld + TILE + mt * 16 * SROW + k16 * 32);
            }
#pragma unroll
            for (int nt2 = 0; nt2 < 4; nt2++)
                ldsm4(bf_[nt2], b_ld + nt2 * 16 * SROW + k16 * 32);
#pragma unroll
            for (int mt = 0; mt < 2; mt++)
#pragma unroll
                for (int nt = 0; nt < 8; nt++)
                    mma16816(acc[mt][nt], ahf[mt], &bf_[nt >> 1][(nt & 1) * 2]);
#pragma unroll
            for (int mt = 0; mt < 2; mt++)
#pragma unroll
                for (int nt = 0; nt < 8; nt++)
                    mma16816(acc[mt][nt], alf[mt], &bf_[nt >> 1][(nt & 1) * 2]);
#pragma unroll
            for (int nt2 = 0; nt2 < 4; nt2++)
                ldsm4(bf_[nt2], b_ld + TILE + nt2 * 16 * SROW + k16 * 32);
#pragma unroll
            for (int mt = 0; mt < 2; mt++)
#pragma unroll
                for (int nt = 0; nt < 8; nt++)
                    mma16816(acc[mt][nt], ahf[mt], &bf_[nt >> 1][(nt & 1) * 2]);
        }
        __syncthreads();
    }

    const int r_in = lane >> 2;
    const int c_in = (lane & 3) * 2;
#pragma unroll
    for (int mt = 0; mt < 2; mt++) {
#pragma unroll
        for (int half = 0; half < 2; half++) {
            const size_t row = (size_t)(m0 + mb + mt * 16 + r_in + half * 8);
#pragma unroll
            for (int nt = 0; nt < 8; nt++) {
                const int c = n0 + nb + nt * 8 + c_in;
                float d0 = acc[mt][nt][half * 2 + 0];
                float d1 = acc[mt][nt][half * 2 + 1];
                if (EPI == 1) {
                    const float* xp = xsrc + row * 256 + c;
                    float x0 = xp[0], x1 = xp[1];
                    float xx0 = d0 + x0, xx1 = d1 + x1;
                    float k0v = x0 * mk[c] + xx0 * (1.f - mk[c]);
                    float k1v = x1 * mk[c + 1] + xx1 * (1.f - mk[c + 1]);
                    float v0v = x0 * mv[c] + xx0 * (1.f - mv[c]);
                    float v1v = x1 * mv[c + 1] + xx1 * (1.f - mv[c + 1]);
                    float r0v = x0 * mr[c] + xx0 * (1.f - mr[c]);
                    float r1v = x1 * mr[c + 1] + xx1 * (1.f - mr[c + 1]);
                    __nv_bfloat16* base = outsp + row * 256 + c;
                    float h0, l0, h1, l1;
                    split1(k0v, h0, l0); split1(k1v, h1, l1);
                    *(uint32_t*)(base)                   = pack_bf16(h0, h1);
                    *(uint32_t*)(base + (size_t)NEL)     = pack_bf16(l0, l1);
                    split1(v0v, h0, l0); split1(v1v, h1, l1);
                    *(uint32_t*)(base + 2 * (size_t)NEL) = pack_bf16(h0, h1);
                    *(uint32_t*)(base + 3 * (size_t)NEL) = pack_bf16(l0, l1);
                    split1(r0v, h0, l0); split1(r1v, h1, l1);
                    *(uint32_t*)(base + 4 * (size_t)NEL) = pack_bf16(h0, h1);
                    *(uint32_t*)(base + 5 * (size_t)NEL) = pack_bf16(l0, l1);
                } else {
                    *(float2*)(ofuse + row * 256 + c) = make_float2(d0, d1);
                }
            }
        }
    }
}

// =====================================================================
// split / prep kernels
// =====================================================================
__global__ void split_pairs(const float* __restrict__ src,
                            __nv_bfloat16* __restrict__ dst, size_t loff)
{
    size_t i = ((size_t)blockIdx.x * 256 + threadIdx.x) * 4;
    float4 v = *(const float4*)(src + i);
    uint32_t h[2], l[2];
    split4(v, h, l);
    *(uint2*)(dst + i) = make_uint2(h[0], h[1]);
    *(uint2*)(dst + loff + i) = make_uint2(l[0], l[1]);
}

__global__ void prep_wcat_sp(const float* __restrict__ p1,
                             const float* __restrict__ p2,
                             const float* __restrict__ p3)
{
    int i = blockIdx.x * 256 + threadIdx.x;
    int n = i / 768;
    int k = i - n * 768;
    const float* src = (k < 256) ? p1 : (k < 512 ? p2 : p3);
    float h, l;
    split1(src[n * 256 + (k & 255)], h, l);
    g_wcat_sp[i] = __float2bfloat16_rn(h);
    g_wcat_sp[196608 + i] = __float2bfloat16_rn(l);
}

__global__ void prep_wkvr_sp(const float* __restrict__ kw,
                             const float* __restrict__ vw,
                             const float* __restrict__ rw)
{
    int i = blockIdx.x * 256 + threadIdx.x;
    int z = i >> 16, idx = i & 65535;
    const float* s = (z == 0) ? kw : (z == 1 ? vw : rw);
    float h, l;
    split1(s[idx], h, l);
    g_wkvr_sp[(size_t)z * 131072 + idx] = __float2bfloat16_rn(h);
    g_wkvr_sp[(size_t)z * 131072 + 65536 + idx] = __float2bfloat16_rn(l);
}

// =====================================================================
// depthwise 3x3 convs -> split bf16 K=768 layout
// =====================================================================
__global__ void dwconv_kernel(const float* __restrict__ w1,
                              const float* __restrict__ w2,
                              const float* __restrict__ w3)
{
    __shared__ float sw[3][256 * 9];
    for (int i = threadIdx.x; i < 256 * 9; i += 256) {
        sw[0][i] = w1[i]; sw[1][i] = w2[i]; sw[2][i] = w3[i];
    }
    __syncthreads();

    const int c = threadIdx.x;
    const int t = blockIdx.x;
    const int b = blockIdx.y;
    const int h = t >> 7, w = t & 127;
    const float* midb = g_mid + (size_t)b * CT * CC;

    float acc1 = 0.f, acc2 = 0.f, acc3 = 0.f;
#pragma unroll
    for (int dy = -1; dy <= 1; dy++) {
#pragma unroll
        for (int dx = -1; dx <= 1; dx++) {
            const int ti = (dy + 1) * 3 + (dx + 1);
            {
                int hh = h + dy, ww = w + dx;
                if ((unsigned)hh < 128u && (unsigned)ww < 128u)
                    acc1 += midb[(size_t)(hh * 128 + ww) * CC + c] * sw[0][c * 9 + ti];
            }
            {
                int hh = h + 2 * dy, ww = w + 2 * dx;
                if ((unsigned)hh < 128u && (unsigned)ww < 128u)
                    acc2 += midb[(size_t)(hh * 128 + ww) * CC + c] * sw[1][c * 9 + ti];
            }
            {
                int hh = h + 3 * dy, ww = w + 3 * dx;
                if ((unsigned)hh < 128u && (unsigned)ww < 128u)
                    acc3 += midb[(size_t)(hh * 128 + ww) * CC + c] * sw[2][c * 9 + ti];
            }
        }
    }
    const size_t row = ((size_t)b * CT + t) * 768;
    const size_t LO = 3 * (size_t)NEL;
    float hh, ll;
    split1(acc1, hh, ll);
    g_dw_sp[row + c] = __float2bfloat16_rn(hh);
    g_dw_sp[LO + row + c] = __float2bfloat16_rn(ll);
    split1(acc2, hh, ll);
    g_dw_sp[row + 256 + c] = __float2bfloat16_rn(hh);
    g_dw_sp[LO + row + 256 + c] = __float2bfloat16_rn(ll);
    split1(acc3, hh, ll);
    g_dw_sp[row + 512 + c] = __float2bfloat16_rn(hh);
    g_dw_sp[LO + row + 512 + c] = __float2bfloat16_rn(ll);
}

// =====================================================================
// WKV chunked parallel scan
// =====================================================================
constexpr int WKV_L = 128;
constexpr int WKV_LB = 64;

__global__ void wkv_kernel(const float* __restrict__ decay,
                           const float* __restrict__ first)
{
    const int c = threadIdx.x;
    const int b = blockIdx.y;
    const int t0 = blockIdx.x * WKV_L;
    int ts = t0 - WKV_LB; if (ts < 0) ts = 0;

    const float lam = expf(-expf(decay[c] * (1.f / CT)));
    const float u = first[c] * (1.f / CT);

    const float* kp = g_kvr + (size_t)b * CT * CC + c;
    const float* vp = kp + NEL;
    float* yp = g_y + (size_t)b * CT * CC + c;

    float a = 0.f, bsum = 0.f;
    for (int t = ts; t < t0; t++) {
        float kk = kp[(size_t)t * CC], vv = vp[(size_t)t * CC];
        float ek = expf(kk);
        a = lam * a + ek * vv;
        bsum = lam * bsum + ek;
    }
    for (int t = t0; t < t0 + WKV_L; t++) {
        float kk = kp[(size_t)t * CC], vv = vp[(size_t)t * CC];
        float e2 = expf(u + kk);
        yp[(size_t)t * CC] = (a + e2 * vv) / (bsum + e2);
        float ek = expf(kk);
        a = lam * a + ek * vv;
        bsum = lam * bsum + ek;
    }
}

// =====================================================================
// LayerNorm + sigmoid gate -> split bf16
// =====================================================================
__global__ void lngate_kernel(const float* __restrict__ gamma,
                              const float* __restrict__ beta)
{
    const int warp = threadIdx.x >> 5;
    const int lane = threadIdx.x & 31;
    const size_t row = (size_t)blockIdx.x * 8 + warp;
    const float* yr = g_y + row * CC;
    const float* rr = g_kvr + 2 * (size_t)NEL + row * CC;

    float vals[8];
    float s = 0.f;
#pragma unroll
    for (int j = 0; j < 8; j++) { vals[j] = yr[lane + 32 * j]; s += vals[j]; }
#pragma unroll
    for (int o = 16; o; o >>= 1) s += __shfl_xor_sync(0xFFFFFFFFu, s, o);
    const float mu = s * (1.f / 256.f);

    float q = 0.f;
#pragma unroll
    for (int j = 0; j < 8; j++) { float d = vals[j] - mu; q += d * d; }
#pragma unroll
    for (int o = 16; o; o >>= 1) q += __shfl_xor_sync(0xFFFFFFFFu, q, o);
    const float rstd = rsqrtf(q * (1.f / 256.f) + 1e-5f);

#pragma unroll
    for (int j = 0; j < 8; j++) {
        int cidx = lane + 32 * j;
        float sr = 1.f / (1.f + expf(-rr[cidx]));
        float g = sr * ((vals[j] - mu) * rstd * gamma[cidx] + beta[cidx]);
        float h, l;
        split1(g, h, l);
        g_gate_sp[row * CC + cidx] = __float2bfloat16_rn(h);
        g_gate_sp[(size_t)NEL + row * CC + cidx] = __float2bfloat16_rn(l);
    }
}

// ---------------- launch ----------------
extern "C" void kernel_launch(void* const* d_in, const int* in_sizes, int n_in,
                              void* d_out, int out_size)
{
    const float* x        = (const float*)d_in[0];
    const float* conv1_w  = (const float*)d_in[1];
    const float* dw1_w    = (const float*)d_in[2];
    const float* dw2_w    = (const float*)d_in[3];
    const float* dw3_w    = (const float*)d_in[4];
    const float* proj1_w  = (const float*)d_in[5];
    const float* proj2_w  = (const float*)d_in[6];
    const float* proj3_w  = (const float*)d_in[7];
    const float* decay    = (const float*)d_in[8];
    const float* first    = (const float*)d_in[9];
    const float* mix_k    = (const float*)d_in[10];
    const float* mix_v    = (const float*)d_in[11];
    const float* mix_r    = (const float*)d_in[12];
    const float* key_w    = (const float*)d_in[13];
    const float* value_w  = (const float*)d_in[14];
    const float* recep_w  = (const float*)d_in[15];
    const float* out_w    = (const float*)d_in[16];
    const float* ln_gamma = (const float*)d_in[17];
    const float* ln_beta  = (const float*)d_in[18];

    __nv_bfloat16 *xsp, *dwsp, *xkvrsp, *gatesp, *w1sp, *wcatsp, *wkvrsp, *wosp;
    float *mid, *kvr;
    cudaGetSymbolAddress((void**)&xsp,    g_x_sp);
    cudaGetSymbolAddress((void**)&mid,    g_mid);
    cudaGetSymbolAddress((void**)&dwsp,   g_dw_sp);
    cudaGetSymbolAddress((void**)&xkvrsp, g_xkvr_sp);
    cudaGetSymbolAddress((void**)&kvr,    g_kvr);
    cudaGetSymbolAddress((void**)&gatesp, g_gate_sp);
    cudaGetSymbolAddress((void**)&w1sp,   g_w1_sp);
    cudaGetSymbolAddress((void**)&wcatsp, g_wcat_sp);
    cudaGetSymbolAddress((void**)&wkvrsp, g_wkvr_sp);
    cudaGetSymbolAddress((void**)&wosp,   g_wo_sp);

    cudaFuncSetAttribute(mma_gemm<256, 0, 1>, cudaFuncAttributeMaxDynamicSharedMemorySize, SMEM_GEMM);
    cudaFuncSetAttribute(mma_gemm<768, 1, 1>, cudaFuncAttributeMaxDynamicSharedMemorySize, SMEM_GEMM);
    cudaFuncSetAttribute(mma_gemm<256, 0, 3>, cudaFuncAttributeMaxDynamicSharedMemorySize, SMEM_GEMM);

    const dim3 gGemm(2, 512);
    const dim3 gGemm3(2, 512, 3);

    // 0) one-time splits: x + all weights
    split_pairs<<<NEL / 1024, 256>>>(x, xsp, NEL);
    split_pairs<<<64, 256>>>(conv1_w, w1sp, 65536);
    split_pairs<<<64, 256>>>(out_w, wosp, 65536);
    prep_wcat_sp<<<768, 256>>>(proj1_w, proj2_w, proj3_w);
    prep_wkvr_sp<<<768, 256>>>(key_w, value_w, recep_w);

    // 1) mid = x @ conv1^T (fp32)
    mma_gemm<256, 0, 1><<<gGemm, 256, SMEM_GEMM>>>(
        xsp, w1sp, nullptr, nullptr, nullptr, nullptr, mid, nullptr);
    // 2) depthwise convs -> split dwcat
    dwconv_kernel<<<dim3(CT, CB), 256>>>(dw1_w, dw2_w, dw3_w);
    // 3) proj GEMM (K=768), fused xx + mix -> split xk|xv|xr
    mma_gemm<768, 1, 1><<<gGemm, 256, SMEM_GEMM>>>(
        dwsp, wcatsp, x, mix_k, mix_v, mix_r, nullptr, xkvrsp);
    // 4) k/v/r projections (batched) -> fp32 kvr
    mma_gemm<256, 0, 3><<<gGemm3, 256, SMEM_GEMM>>>(
        xkvrsp, wkvrsp, nullptr, nullptr, nullptr, nullptr, kvr, nullptr);
    // 5) WKV scan
    wkv_kernel<<<dim3(CT / WKV_L, CB), 256>>>(decay, first);
    // 6) LN + gate -> split gate
    lngate_kernel<<<CM / 8, 256>>>(ln_gamma, ln_beta);
    // 7) output projection -> d_out
    mma_gemm<256, 0, 1><<<gGemm, 256, SMEM_GEMM>>>(
        gatesp, wosp, nullptr, nullptr, nullptr, nullptr, (float*)d_out, nullptr);
}